// round 9
// baseline (speedup 1.0000x reference)
#include <cuda_runtime.h>
#include <math.h>

// Fixed problem shapes
#define Bv   16
#define Cc   256
#define Nn   64
#define NN   4096
#define Ss   128
#define EPSN 1e-12f
#define SCALE 10.0f
#define TPB  512     // 4 teams x 128 threads

typedef unsigned long long ull;

// Scratch: normalized sentence features + offsets
__device__ float g_sn1[Ss * Cc];
__device__ float g_sn2[Ss * Cc];
__device__ int   g_off[Bv + 1];

// Packed dual-fp32 FMA / ADD (Blackwell)
#define FFMA2(acc, a, bb) \
    asm("fma.rn.f32x2 %0, %1, %2, %0;" : "+l"(acc) : "l"(a), "l"(bb))
#define FADD2(dst, a, bb) \
    asm("add.rn.f32x2 %0, %1, %2;" : "=l"(dst) : "l"(a), "l"(bb))

// cp.async: 8-byte global->shared, per-warp commit/wait pipeline
#define CP_ASYNC8(dst_u32, src_ptr) \
    asm volatile("cp.async.ca.shared.global [%0], [%1], 8;" \
                 :: "r"(dst_u32), "l"(src_ptr) : "memory")
#define CP_COMMIT() \
    asm volatile("cp.async.commit_group;" ::: "memory")
#define CP_WAIT7() \
    asm volatile("cp.async.wait_group 7;" ::: "memory")
#define CP_WAIT0() \
    asm volatile("cp.async.wait_group 0;" ::: "memory")

__device__ __forceinline__ float f2lo(ull x) {
    return __uint_as_float((unsigned)(x & 0xffffffffu));
}
__device__ __forceinline__ float f2hi(ull x) {
    return __uint_as_float((unsigned)(x >> 32));
}
__device__ __forceinline__ ull dup32(unsigned x) {
    ull d;
    asm("mov.b64 %0, {%1, %1};" : "=l"(d) : "r"(x));
    return d;
}
__device__ __forceinline__ unsigned smem_u32(const void* p) {
    return (unsigned)__cvta_generic_to_shared(p);
}

// ---------------------------------------------------------------------------
// Kernel 1: normalize sentence features (warp per row) + prefix offsets
// ---------------------------------------------------------------------------
__global__ void prep_kernel(const float* __restrict__ sf1,
                            const float* __restrict__ sf2,
                            const int*   __restrict__ nums) {
    if (blockIdx.x == 0 && threadIdx.x == 0) {
        int acc = 0;
        g_off[0] = 0;
        #pragma unroll
        for (int i = 0; i < Bv; i++) { acc += nums[i]; g_off[i + 1] = acc; }
    }
    int warp = threadIdx.x >> 5;
    int lane = threadIdx.x & 31;
    int row  = blockIdx.x * 8 + warp;   // 2S rows
    const float* src;
    float* dst;
    if (row < Ss) { src = sf1 + (size_t)row * Cc;        dst = g_sn1 + (size_t)row * Cc; }
    else          { src = sf2 + (size_t)(row - Ss) * Cc; dst = g_sn2 + (size_t)(row - Ss) * Cc; }

    float v[8];
    float sum = 0.f;
    #pragma unroll
    for (int k = 0; k < 8; k++) {
        v[k] = src[lane + 32 * k];
        sum += v[k] * v[k];
    }
    #pragma unroll
    for (int o = 16; o; o >>= 1) sum += __shfl_xor_sync(0xffffffffu, sum, o);
    float inv = 1.f / fmaxf(sqrtf(sum), EPSN);
    #pragma unroll
    for (int k = 0; k < 8; k++) dst[lane + 32 * k] = v[k] * inv;
}

// ---------------------------------------------------------------------------
// Kernel 2: fused dual-space scoring, cp.async video pipeline.
// Block = 512 thr = 4 teams x 128. team = (space sp, channel-half ch).
// Thread owns 2 adjacent columns; FFMA2 lanes = (sent 2p, sent 2p+1)
// (unduplicated sentence smem, 2 LDS.128/channel). Video is streamed via a
// per-warp 8-slot cp.async smem ring (LDGSTS has no observed in-flight
// depth cap and holds no registers) -> ~1.9 KB of DRAM bytes in flight per
// warp. No barriers in the mainloop. Partials via smem; team 0 epilogue.
// grid = (16,16), block 512. Static smem = 16K sent + 32K ring = 48 KB.
// ---------------------------------------------------------------------------
__global__ __launch_bounds__(TPB, 2) void score_kernel(
    const float* __restrict__ vf1,
    const float* __restrict__ vf2,
    const float* __restrict__ mask2d,
    float* __restrict__ out) {

    // sentence pairs: idx sp*1024 + (ch*128+k)*4 + p   (2048 ull, 16 KB)
    __shared__ __align__(16) ull sent[2048];
    // video ring: team*1024 + slot*128 + ttid (4096 ull, 32 KB);
    // aliased as reduction scratch (needs 3*128*9 = 3456 ull) post-loop.
    __shared__ __align__(16) ull vbuf[4096];

    const int tid  = threadIdx.x;
    const int team = tid >> 7;       // 0..3
    const int ttid = tid & 127;
    const int sp   = team >> 1;      // feature space
    const int ch   = team & 1;       // channel half
    const int b    = blockIdx.y;
    const int ij0  = blockIdx.x * 256 + 2 * ttid;

    const int start = g_off[b];
    int end = g_off[b + 1];
    if (end > Ss) end = Ss;
    if (start >= end) return;        // uniform per block

    const float* vf = (sp == 0) ? vf1 : vf2;
    const ull* __restrict__ v = reinterpret_cast<const ull*>(
        vf + ((size_t)b * Cc + (size_t)ch * 128) * NN + ij0);

    const ull* __restrict__ sb = sent + (size_t)sp * 1024 + (size_t)ch * 512;
    ull* __restrict__ vslots = vbuf + (size_t)team * 1024 + ttid;
    const unsigned vb_u32 = smem_u32(vslots);

    for (int cs = start; cs < end; cs += 8) {
        const int cnt = min(8, end - cs);

        // Stage sentence pairs {s2p, s2p+1}: 2048 ull, all 512 threads
        for (int e = tid; e < 2048; e += TPB) {
            const int p   = e & 3;
            const int c   = (e >> 2) & (Cc - 1);
            const int spp = e >> 10;
            const float* g = spp ? g_sn2 : g_sn1;
            float x0 = 0.f, x1 = 0.f;
            if (2 * p < cnt)     x0 = g[(size_t)(cs + 2 * p) * Cc + c];
            if (2 * p + 1 < cnt) x1 = g[(size_t)(cs + 2 * p + 1) * Cc + c];
            float2 d = make_float2(x0, x1);
            sent[e] = *reinterpret_cast<ull*>(&d);
        }
        __syncthreads();

        // acc[p*2+c]: lanes = (sent 2p, sent 2p+1), c = column 0/1
        ull acc[8];
        #pragma unroll
        for (int s = 0; s < 8; s++) acc[s] = 0ull;
        ull nrm = 0ull;                 // lanes = (col0, col1)

        // ---- cp.async ring: preload channels 0..6 ----
        #pragma unroll
        for (int i = 0; i < 7; i++) {
            CP_ASYNC8(vb_u32 + i * 1024u, v + (size_t)i * (NN / 2));
            CP_COMMIT();
        }

        #pragma unroll 4
        for (int k = 0; k < 128; k++) {
            const int kp = k + 7;
            if (kp < 128)
                CP_ASYNC8(vb_u32 + (unsigned)(kp & 7) * 1024u,
                          v + (size_t)kp * (NN / 2));
            CP_COMMIT();
            CP_WAIT7();                 // channel k's slot is ready

            const ull a = vslots[(size_t)(k & 7) * 128];
            FFMA2(nrm, a, a);
            const ull d0 = dup32((unsigned)a);
            const ull d1 = dup32((unsigned)(a >> 32));
            const ulonglong2* p2 =
                reinterpret_cast<const ulonglong2*>(sb + k * 4);
            const ulonglong2 q0 = p2[0];   // {s0,s1},{s2,s3}
            FFMA2(acc[0], d0, q0.x); FFMA2(acc[1], d1, q0.x);
            FFMA2(acc[2], d0, q0.y); FFMA2(acc[3], d1, q0.y);
            const ulonglong2 q1 = p2[1];   // {s4,s5},{s6,s7}
            FFMA2(acc[4], d0, q1.x); FFMA2(acc[5], d1, q1.x);
            FFMA2(acc[6], d0, q1.y); FFMA2(acc[7], d1, q1.y);
        }
        CP_WAIT0();        // drain trailing (empty) groups
        __syncthreads();   // all ring reads done; vbuf -> reduce scratch

        // Teams 1..3 publish partials (9 ull each) into vbuf
        if (team != 0) {
            ull* r = vbuf + ((size_t)(team - 1) * 128 + ttid) * 9;
            #pragma unroll
            for (int s = 0; s < 8; s++) r[s] = acc[s];
            r[8] = nrm;
        }
        __syncthreads();

        if (team == 0) {
            const ull* r1 = vbuf + ((size_t)0 * 128 + ttid) * 9; // sp0, ch1
            const ull* r2 = vbuf + ((size_t)1 * 128 + ttid) * 9; // sp1, ch0
            const ull* r3 = vbuf + ((size_t)2 * 128 + ttid) * 9; // sp1, ch1

            ull t1[8], t2[8], n1, n2;
            #pragma unroll
            for (int s = 0; s < 8; s++) {
                FADD2(t1[s], acc[s], r1[s]);
                FADD2(t2[s], r2[s], r3[s]);
            }
            FADD2(n1, nrm, r1[8]);
            FADD2(n2, r2[8], r3[8]);

            // n lanes = (col0, col1)
            const float i1c0 = 1.f / fmaxf(sqrtf(f2lo(n1)), EPSN);
            const float i1c1 = 1.f / fmaxf(sqrtf(f2hi(n1)), EPSN);
            const float i2c0 = 1.f / fmaxf(sqrtf(f2lo(n2)), EPSN);
            const float i2c1 = 1.f / fmaxf(sqrtf(f2hi(n2)), EPSN);

            const float2 mv = *reinterpret_cast<const float2*>(mask2d + ij0);
            const float m0 = mv.x, m1 = mv.y;

            for (int s = 0; s < cnt; s++) {
                const size_t srow = (size_t)(cs + s);
                const int p = s >> 1;
                const bool hi = (s & 1) != 0;
                const float d1c0 = hi ? f2hi(t1[p * 2 + 0]) : f2lo(t1[p * 2 + 0]);
                const float d1c1 = hi ? f2hi(t1[p * 2 + 1]) : f2lo(t1[p * 2 + 1]);
                const float d2c0 = hi ? f2hi(t2[p * 2 + 0]) : f2lo(t2[p * 2 + 0]);
                const float d2c1 = hi ? f2hi(t2[p * 2 + 1]) : f2lo(t2[p * 2 + 1]);

                const float lglo = SCALE * (d1c0 * i1c0);
                const float lghi = SCALE * (d1c1 * i1c1);
                *reinterpret_cast<float2*>(out + srow * NN + ij0) =
                    make_float2(lglo, lghi);

                const float ioulo = m0 / (1.f + __expf(-lglo));
                const float iouhi = m1 / (1.f + __expf(-lghi));
                const float conlo =
                    fmaxf((d2c0 * i2c0 + 1.f) * 0.5f * m0, 0.f);
                const float conhi =
                    fmaxf((d2c1 * i2c1 + 1.f) * 0.5f * m1, 0.f);
                *reinterpret_cast<float2*>(
                    out + (size_t)Ss * NN + srow * NN + ij0) =
                    make_float2(sqrtf(conlo) * ioulo, sqrtf(conhi) * iouhi);
            }
        }
        __syncthreads();   // sent/vbuf safe to restage
    }
}

// ---------------------------------------------------------------------------
extern "C" void kernel_launch(void* const* d_in, const int* in_sizes, int n_in,
                              void* d_out, int out_size) {
    const float* vf1  = (const float*)d_in[0];
    const float* vf2  = (const float*)d_in[1];
    const float* sf1  = (const float*)d_in[2];
    const float* sf2  = (const float*)d_in[3];
    const float* mask = (const float*)d_in[4];
    const int*   nums = (const int*)d_in[5];
    float* out = (float*)d_out;

    prep_kernel<<<(2 * Ss) / 8, 256>>>(sf1, sf2, nums);
    score_kernel<<<dim3(NN / 256, Bv), TPB>>>(vf1, vf2, mask, out);
}